// round 14
// baseline (speedup 1.0000x reference)
#include <cuda_runtime.h>
#include <cuda_bf16.h>
#include <math.h>
#include <stdint.h>

#define BATCH   2
#define LSEQ    2048
#define DMODEL  1024
#define NHEADS  16
#define DHEAD   64
#define NKT     (LSEQ / 64)
#define NQT     (LSEQ / 128)

#define MROWS   (BATCH * LSEQ)      // 4096
#define XSZ     (MROWS * DMODEL)    // 4194304
#define WSZ     (DMODEL * DMODEL)   // 1048576

// ---------------- scratch (allocation-free: __device__ globals) ----------------
__device__ float g_vw[XSZ];
__device__ int   g_kmax[BATCH];
__device__ float g_cnt[BATCH];
__device__ __nv_bfloat16 g_xh[3 * XSZ];
__device__ __nv_bfloat16 g_xl[3 * XSZ];
__device__ __nv_bfloat16 g_wh[3 * WSZ];
__device__ __nv_bfloat16 g_wl[3 * WSZ];
__device__ __nv_bfloat16 g_qsh[XSZ], g_qsl[XSZ];  // Q proj (pre-scaled by CSC), hi/lo
__device__ __nv_bfloat16 g_ksh[XSZ], g_ksl[XSZ];  // K proj, hi/lo
__device__ __nv_bfloat16 g_vth[XSZ], g_vtl[XSZ];  // V proj transposed, hi/lo

// ============================ PTX helpers (portable sm_80+) ====================
__device__ __forceinline__ uint32_t smem_u32(const void* p) {
    uint32_t a;
    asm("{ .reg .u64 t; cvta.to.shared.u64 t, %1; cvt.u32.u64 %0, t; }" : "=r"(a) : "l"(p));
    return a;
}
#define CP_ASYNC16(dst, src) \
    asm volatile("cp.async.cg.shared.global [%0], [%1], 16;" :: "r"(dst), "l"(src) : "memory")
#define CP_COMMIT() asm volatile("cp.async.commit_group;" ::: "memory")
#define CP_WAIT1()  asm volatile("cp.async.wait_group 1;" ::: "memory")
#define CP_WAIT0()  asm volatile("cp.async.wait_group 0;" ::: "memory")

#define LDSM_X4(R0, R1, R2, R3, ADDR) \
    asm volatile("ldmatrix.sync.aligned.m8n8.x4.shared.b16 {%0,%1,%2,%3}, [%4];" \
                 : "=r"(R0), "=r"(R1), "=r"(R2), "=r"(R3) : "r"(ADDR))

#define MMA_BF16(C0, C1, C2, C3, A0, A1, A2, A3, B0, B1) \
    asm volatile("mma.sync.aligned.m16n8k16.row.col.f32.bf16.bf16.f32 " \
                 "{%0,%1,%2,%3}, {%4,%5,%6,%7}, {%8,%9}, {%0,%1,%2,%3};" \
                 : "+f"(C0), "+f"(C1), "+f"(C2), "+f"(C3) \
                 : "r"(A0), "r"(A1), "r"(A2), "r"(A3), "r"(B0), "r"(B1))

#define PACK_BF16X2(R, A, B) \
    asm("cvt.rn.bf16x2.f32 %0, %1, %2;" : "=r"(R) : "f"(B), "f"(A))

// fast 2^x, no clamp. FMA pipes only. rel err ~2.4e-6.
__device__ __forceinline__ float fexp2nc(float x) {
    float t = x + 12582912.f;
    float n = t - 12582912.f;
    float f = x - n;
    float p = 1.3333558e-3f;
    p = fmaf(p, f, 9.6181291e-3f);
    p = fmaf(p, f, 5.5504109e-2f);
    p = fmaf(p, f, 2.4022651e-1f);
    p = fmaf(p, f, 6.9314718e-1f);
    p = fmaf(p, f, 1.0f);
    int sc = (__float_as_int(t) + (127 - 0x4B400000)) << 23;
    return p * __int_as_float(sc);
}

__device__ __forceinline__ void split1(float x, __nv_bfloat16& h, __nv_bfloat16& l) {
    h = __float2bfloat16_rn(x);
    l = __float2bfloat16_rn(x - __bfloat162float(h));
}
__device__ __forceinline__ void packsplit2(float a, float b, uint32_t& hi, uint32_t& lo) {
    PACK_BF16X2(hi, a, b);
    float ra = __uint_as_float(hi << 16);
    float rb = __uint_as_float(hi & 0xFFFF0000u);
    PACK_BF16X2(lo, a - ra, b - rb);
}

#define CSC 0.18033688f   /* 0.125 * log2(e), folded into Q at projection */

// ================= fp32 -> bf16 hi/lo split (x and W in one launch) ============
#define XBLK (XSZ / 4 / 256)   // 4096 blocks for the activation tensor
__global__ void split2_kernel(const float* __restrict__ xs,
                              const float* __restrict__ ws, int sel)
{
    const int blk = blockIdx.x;
    const float* src;
    __nv_bfloat16* hi;
    __nv_bfloat16* lo;
    int i;
    if (blk < XBLK) {
        i = blk * 256 + threadIdx.x;
        src = xs;
        hi = g_xh + (size_t)sel * XSZ; lo = g_xl + (size_t)sel * XSZ;
    } else {
        i = (blk - XBLK) * 256 + threadIdx.x;
        src = ws;
        hi = g_wh + (size_t)sel * WSZ; lo = g_wl + (size_t)sel * WSZ;
    }
    float4 x = ((const float4*)src)[i];
    __nv_bfloat162 h01, h23, l01, l23;
    split1(x.x, h01.x, l01.x); split1(x.y, h01.y, l01.y);
    split1(x.z, h23.x, l23.x); split1(x.w, h23.y, l23.y);
    ((__nv_bfloat162*)hi)[2 * i]     = h01;
    ((__nv_bfloat162*)hi)[2 * i + 1] = h23;
    ((__nv_bfloat162*)lo)[2 * i]     = l01;
    ((__nv_bfloat162*)lo)[2 * i + 1] = l23;
}

// ====== mma.sync projection GEMM: CTA 128x128, warp tile 64x32, 2 CTAs/SM ======
// 64 accs/thread, K-chunk 32, pad-40 rows (conflict-free LDSM), 80KB smem ->
// __launch_bounds__(256,2) gives 16 warps/SM for latency hiding.
#define GK        32
#define GPAD      40
#define NCHUNK    (DMODEL / GK)             // 32
#define GBUF      (128 * GPAD)              // 5120 elements per buffer
#define STAGE_ELEMS (4 * GBUF)              // Ah Al Bh Bl = 20480
#define GEMM_SMEM (2 * STAGE_ELEMS * 2)     // 81920 bytes

__global__ __launch_bounds__(256, 2) void gemm_kernel()
{
    extern __shared__ __nv_bfloat16 gsm[];
    const int sel = blockIdx.z;
    const int n0  = blockIdx.x * 128;
    const int m0  = blockIdx.y * 128;
    const int t   = threadIdx.x;
    const int w   = t >> 5, l = t & 31;

    const __nv_bfloat16* __restrict__ Ah = g_xh + (size_t)sel * XSZ;
    const __nv_bfloat16* __restrict__ Al = g_xl + (size_t)sel * XSZ;
    const __nv_bfloat16* __restrict__ Bh = g_wh + (size_t)sel * WSZ;
    const __nv_bfloat16* __restrict__ Bl = g_wl + (size_t)sel * WSZ;

    auto issue = [&](int c, int s) {
        __nv_bfloat16* base = gsm + s * STAGE_ELEMS;
        const int k0 = c * GK;
#pragma unroll
        for (int i = 0; i < 8; i++) {           // 2048 x 16B total
            const int cid = t + i * 256;
            const int buf = cid >> 9;           // 0..3 (512 segs per buf)
            const int row = (cid >> 2) & 127;
            const int seg = cid & 3;            // 4 x 8 el = 32 el per row
            const __nv_bfloat16* g;
            int rb;
            if      (buf == 0) { g = Ah; rb = m0; }
            else if (buf == 1) { g = Al; rb = m0; }
            else if (buf == 2) { g = Bh; rb = n0; }
            else               { g = Bl; rb = n0; }
            const __nv_bfloat16* src = g + (size_t)(rb + row) * DMODEL + k0 + seg * 8;
            CP_ASYNC16(smem_u32(base + (size_t)buf * GBUF + row * GPAD + seg * 8), src);
        }
        CP_COMMIT();
    };

    const int wm = (w >> 2) * 64;   // 0 or 64
    const int wn = (w & 3) * 32;    // 0,32,64,96
    const int laneRowA = l & 15;
    const int laneColA = (l >> 4) * 8;
    const int laneRowB = (l >> 4) * 8 + (l & 7);
    const int laneColB = ((l >> 3) & 1) * 8;

    float acc[4][4][4];
#pragma unroll
    for (int mf = 0; mf < 4; mf++)
#pragma unroll
        for (int nf = 0; nf < 4; nf++)
#pragma unroll
            for (int i = 0; i < 4; i++) acc[mf][nf][i] = 0.f;

    issue(0, 0);

    for (int c = 0; c < NCHUNK; c++) {
        if (c + 1 < NCHUNK) { issue(c + 1, (c + 1) & 1); CP_WAIT1(); }
        else                { CP_WAIT0(); }
        __syncthreads();

        const uint32_t stage = smem_u32(gsm) + (uint32_t)((c & 1) * STAGE_ELEMS) * 2;
        const uint32_t xh0 = stage;
        const uint32_t xl0 = stage + GBUF * 2;
        const uint32_t wh0 = stage + 2 * GBUF * 2;
        const uint32_t wl0 = stage + 3 * GBUF * 2;

#pragma unroll
        for (int ks = 0; ks < 2; ks++) {
            const int kc = ks * 16;
            uint32_t ah[4][4], al[4][4], bh[2][4], bl[2][4];
#pragma unroll
            for (int mf = 0; mf < 4; mf++) {
                const uint32_t off = (uint32_t)((wm + mf * 16 + laneRowA) * GPAD + kc + laneColA) * 2;
                LDSM_X4(ah[mf][0], ah[mf][1], ah[mf][2], ah[mf][3], xh0 + off);
                LDSM_X4(al[mf][0], al[mf][1], al[mf][2], al[mf][3], xl0 + off);
            }
#pragma unroll
            for (int g2 = 0; g2 < 2; g2++) {
                const uint32_t off = (uint32_t)((wn + g2 * 16 + laneRowB) * GPAD + kc + laneColB) * 2;
                LDSM_X4(bh[g2][0], bh[g2][1], bh[g2][2], bh[g2][3], wh0 + off);
                LDSM_X4(bl[g2][0], bl[g2][1], bl[g2][2], bl[g2][3], wl0 + off);
            }
#pragma unroll
            for (int mf = 0; mf < 4; mf++) {
#pragma unroll
                for (int nf = 0; nf < 4; nf++) {
                    const int g2 = nf >> 1, hb = (nf & 1) * 2;
                    float* a4 = acc[mf][nf];
                    MMA_BF16(a4[0], a4[1], a4[2], a4[3],
                             ah[mf][0], ah[mf][1], ah[mf][2], ah[mf][3],
                             bh[g2][hb], bh[g2][hb + 1]);
                    MMA_BF16(a4[0], a4[1], a4[2], a4[3],
                             ah[mf][0], ah[mf][1], ah[mf][2], ah[mf][3],
                             bl[g2][hb], bl[g2][hb + 1]);
                    MMA_BF16(a4[0], a4[1], a4[2], a4[3],
                             al[mf][0], al[mf][1], al[mf][2], al[mf][3],
                             bh[g2][hb], bh[g2][hb + 1]);
                }
            }
        }
        __syncthreads();
    }

    const int cr = l >> 2;
    const int cc = (l & 3) * 2;
#pragma unroll
    for (int mf = 0; mf < 4; mf++) {
#pragma unroll
        for (int nf = 0; nf < 4; nf++) {
            const int row = m0 + wm + mf * 16 + cr;
            const int col = n0 + wn + nf * 8 + cc;
            float a0 = acc[mf][nf][0], a1 = acc[mf][nf][1];
            float a2 = acc[mf][nf][2], a3 = acc[mf][nf][3];
            if (sel == 2) {
                float2 v0; v0.x = a0; v0.y = a1;
                float2 v1; v1.x = a2; v1.y = a3;
                *(float2*)&g_vw[(size_t)row * DMODEL + col]       = v0;
                *(float2*)&g_vw[(size_t)(row + 8) * DMODEL + col] = v1;
                const int b = row >> 11, sq = row & 2047;
                const int hh = col >> 6, dd = col & 63;
                const size_t tb = (size_t)(b * NHEADS + hh) * 64;
                __nv_bfloat16 h, lo2;
                split1(a0, h, lo2);
                g_vth[(tb + dd) * LSEQ + sq] = h;     g_vtl[(tb + dd) * LSEQ + sq] = lo2;
                split1(a1, h, lo2);
                g_vth[(tb + dd + 1) * LSEQ + sq] = h; g_vtl[(tb + dd + 1) * LSEQ + sq] = lo2;
                split1(a2, h, lo2);
                g_vth[(tb + dd) * LSEQ + sq + 8] = h; g_vtl[(tb + dd) * LSEQ + sq + 8] = lo2;
                split1(a3, h, lo2);
                g_vth[(tb + dd + 1) * LSEQ + sq + 8] = h; g_vtl[(tb + dd + 1) * LSEQ + sq + 8] = lo2;
            } else {
                __nv_bfloat16* H;
                __nv_bfloat16* L;
                if (sel == 1) { H = g_ksh; L = g_ksl; }
                else {
                    H = g_qsh; L = g_qsl;
                    a0 *= CSC; a1 *= CSC; a2 *= CSC; a3 *= CSC;
                }
                __nv_bfloat162 h0, l0, h1, l1;
                split1(a0, h0.x, l0.x); split1(a1, h0.y, l0.y);
                split1(a2, h1.x, l1.x); split1(a3, h1.y, l1.y);
                *(__nv_bfloat162*)&H[(size_t)row * DMODEL + col]       = h0;
                *(__nv_bfloat162*)&L[(size_t)row * DMODEL + col]       = l0;
                *(__nv_bfloat162*)&H[(size_t)(row + 8) * DMODEL + col] = h1;
                *(__nv_bfloat162*)&L[(size_t)(row + 8) * DMODEL + col] = l1;
            }
        }
    }
}

// ---------------- per-batch mask stats ----------------------------------------
__global__ void mask_stats_kernel(const float* __restrict__ v_mask)
{
    const int b = blockIdx.x;
    const int t = threadIdx.x;
    __shared__ int   smax[256];
    __shared__ float scnt[256];
    int   km = -1;
    float c  = 0.f;
    for (int k = t; k < LSEQ; k += 256) {
        if (v_mask[(size_t)b * LSEQ + k] != 0.f) { km = k; c += 1.f; }
    }
    smax[t] = km; scnt[t] = c;
    __syncthreads();
    for (int s = 128; s > 0; s >>= 1) {
        if (t < s) {
            smax[t] = max(smax[t], smax[t + s]);
            scnt[t] += scnt[t + s];
        }
        __syncthreads();
    }
    if (t == 0) {
        g_kmax[b] = (smax[0] < 0) ? 0 : smax[0];
        g_cnt[b]  = scnt[0];
    }
}

// ========= tensor-core flash attention: q-tile 128, pipelined k-tiles 64 =======
#define AP 72
#define KVBUF (64 * AP)
#define NKVB  4
#define ATTN_SMEM ((2 * 128 * AP + 2 * NKVB * KVBUF) * 2 + 2 * 64 * 4)

__global__ __launch_bounds__(256) void attn_kernel(const float* __restrict__ v_mask,
                                                   const float* __restrict__ q_mask,
                                                   float* __restrict__ out)
{
    extern __shared__ __nv_bfloat16 ash[];
    __nv_bfloat16* Qh = ash;
    __nv_bfloat16* Ql = Qh + 128 * AP;
    __nv_bfloat16* KV = Ql + 128 * AP;
    float* vms = (float*)(KV + 2 * NKVB * KVBUF);

    const int qt = blockIdx.x, h = blockIdx.y, b = blockIdx.z;
    const int t = threadIdx.x, w = t >> 5, l = t & 31;

    const size_t kbase  = (size_t)b * LSEQ * DMODEL + h * 64;
    const size_t vtbase = (size_t)(b * NHEADS + h) * 64 * LSEQ;
    const size_t vmbase = (size_t)b * LSEQ;

    auto issueKV = [&](int kt, int st) {
#pragma unroll
        for (int i = 0; i < 8; i++) {
            const int cid = t + i * 256;
            const int buf = cid >> 9;
            const int row = (cid >> 3) & 63;
            const int s8  = cid & 7;
            const __nv_bfloat16* src;
            if      (buf == 0) src = g_ksh + kbase + (size_t)(kt * 64 + row) * DMODEL + s8 * 8;
            else if (buf == 1) src = g_ksl + kbase + (size_t)(kt * 64 + row) * DMODEL + s8 * 8;
            else if (buf == 2) src = g_vth + vtbase + (size_t)row * LSEQ + kt * 64 + s8 * 8;
            else               src = g_vtl + vtbase + (size_t)row * LSEQ + kt * 64 + s8 * 8;
            CP_ASYNC16(smem_u32(KV + ((size_t)(st * NKVB + buf)) * KVBUF + row * AP + s8 * 8), src);
        }
        if (t < 16)
            CP_ASYNC16(smem_u32(vms + st * 64 + t * 4), v_mask + vmbase + kt * 64 + t * 4);
        CP_COMMIT();
    };

    {
#pragma unroll
        for (int i = 0; i < 8; i++) {
            const int cid = t + i * 256;
            const int hl  = cid >> 10;
            const int row = (cid >> 3) & 127;
            const int s8  = cid & 7;
            const size_t goff = ((size_t)(b * LSEQ + qt * 128 + row)) * DMODEL + h * 64 + s8 * 8;
            const __nv_bfloat16* src = hl ? (g_qsl + goff) : (g_qsh + goff);
            __nv_bfloat16* dst = hl ? (Ql + row * AP + s8 * 8) : (Qh + row * AP + s8 * 8);
            CP_ASYNC16(smem_u32(dst), src);
        }
        CP_COMMIT();
    }

    const int kt0 = qt * 2;
    issueKV(kt0, 0);
    CP_WAIT0();
    __syncthreads();

    const int laneRowA = l & 15;
    const int laneColA = (l >> 4) * 8;
    const int laneRowB = (l >> 4) * 8 + (l & 7);
    const int laneColB = ((l >> 3) & 1) * 8;

    uint32_t aQh[4][4], aQl[4][4];
#pragma unroll
    for (int ks = 0; ks < 4; ks++) {
        const uint32_t off = (uint32_t)((w * 16 + laneRowA) * AP + ks * 16 + laneColA) * 2;
        LDSM_X4(aQh[ks][0], aQh[ks][1], aQh[ks][2], aQh[ks][3], smem_u32(Qh) + off);
        LDSM_X4(aQl[ks][0], aQl[ks][1], aQl[ks][2], aQl[ks][3], smem_u32(Ql) + off);
    }

    float sO[8][4];
#pragma unroll
    for (int df = 0; df < 8; df++)
#pragma unroll
        for (int i = 0; i < 4; i++) sO[df][i] = 0.f;
    float l0 = 0.f, l1 = 0.f;

    const int qrow0 = qt * 128 + w * 16 + (l >> 2);
    const int qrow1 = qrow0 + 8;

    for (int kt = kt0; kt < NKT; kt++) {
        const int st = (kt - kt0) & 1;
        if (kt > kt0) { CP_WAIT0(); }
        __syncthreads();
        if (kt + 1 < NKT) issueKV(kt + 1, st ^ 1);

        const uint32_t Khs = smem_u32(KV + (size_t)(st * NKVB + 0) * KVBUF);
        const uint32_t Kls = smem_u32(KV + (size_t)(st * NKVB + 1) * KVBUF);
        const uint32_t Vhs = smem_u32(KV + (size_t)(st * NKVB + 2) * KVBUF);
        const uint32_t Vls = smem_u32(KV + (size_t)(st * NKVB + 3) * KVBUF);
        const float* vmsb = vms + st * 64;

        float s[8][4];
#pragma unroll
        for (int nf = 0; nf < 8; nf++)
#pragma unroll
            for (int i = 0; i < 4; i++) s[nf][i] = 0.f;
#pragma unroll
        for (int ks = 0; ks < 4; ks++) {
            uint32_t kbh[4][4], kbl[4][4];
#pragma unroll
            for (int g2 = 0; g2 < 4; g2++) {
                const uint32_t off = (uint32_t)((g2 * 16 + laneRowB) * AP + ks * 16 + laneColB) * 2;
                LDSM_X4(kbh[g2][0], kbh[g2][1], kbh[g2][2], kbh[g2][3], Khs + off);
                LDSM_X4(kbl[g2][0], kbl[g2][1], kbl[g2][2], kbl[g2][3], Kls + off);
            }
#pragma unroll
            for (int nf = 0; nf < 8; nf++) {
                const int g2 = nf >> 1, hb = (nf & 1) * 2;
                float* a4 = s[nf];
                MMA_BF16(a4[0], a4[1], a4[2], a4[3],
                         aQh[ks][0], aQh[ks][1], aQh[ks][2], aQh[ks][3],
                         kbh[g2][hb], kbh[g2][hb + 1]);
                MMA_BF16(a4[0], a4[1], a4[2], a4[3],
                         aQh[ks][0], aQh[ks][1], aQh[ks][2], aQh[ks][3],
                         kbl[g2][hb], kbl[g2][hb + 1]);
                MMA_BF16(a4[0], a4[1], a4[2], a4[3],
                         aQl[ks][0], aQl[ks][1], aQl[ks][2], aQl[ks][3],
                         kbh[g2][hb], kbh[g2][hb + 1]);
            }
        }

        if (kt <= kt0 + 1) {
#pragma unroll
            for (int nf = 0; nf < 8; nf++) {
                const int cl0 = nf * 8 + 2 * (l & 3);
                const float vm0 = vmsb[cl0], vm1 = vmsb[cl0 + 1];
                const int c0 = kt * 64 + cl0, c1 = c0 + 1;
                const float m00 = (c0 > qrow0) ? vm0 : 0.f;
                const float m10 = (c1 > qrow0) ? vm1 : 0.f;
                const float m01 = (c0 > qrow1) ? vm0 : 0.f;
                const float m11 = (c1 > qrow1) ? vm1 : 0.f;
                float p0 = fexp2nc(s[nf][0]) * m00;
                float p1 = fexp2nc(s[nf][1]) * m10;
                float p2 = fexp2nc(s[nf][2]) * m01;
                float p3 = fexp2nc(s[nf][3]) * m11;
                l0 += p0 + p1;
                l1 += p2 + p3;
                s[nf][0] = p0; s[nf][1] = p1; s[nf][2] = p2; s[nf][3] = p3;
            }
        } else {
#pragma unroll
            for (int nf = 0; nf < 8; nf++) {
                const int cl0 = nf * 8 + 2 * (l & 3);
                const float vm0 = vmsb[cl0], vm1 = vmsb[cl0 + 1];
                float p0 = fexp2nc(s[nf][0]) * vm0;
                float p1 = fexp2nc(s[nf][1]) * vm1;
                float p2 = fexp2nc(s[nf][2]) * vm0;
                float p3 = fexp2nc(s[nf][3]) * vm1;
                l0 += p0 + p1;
                l1 += p2 + p3;
                s[nf][0] = p0; s[nf][1] = p1; s[nf][2] = p2; s[nf][3] = p3;
            }
        }

#pragma unroll
        for (int kv = 0; kv < 4; kv++) {
            uint32_t aPh[4], aPl[4];
            packsplit2(s[2 * kv][0],     s[2 * kv][1],     aPh[0], aPl[0]);
            packsplit2(s[2 * kv][2],     s[2 * kv][3],     aPh[1], aPl[1]);
            packsplit2(s[2 * kv + 1][0], s[2 * kv + 1][1], aPh[2], aPl[2]);
            packsplit2(s[2 * kv + 1][2], s[2 * kv + 1][3], aPh[3], aPl[3]);
            uint32_t vbh[4][4], vbl[4][4];
#pragma unroll
            for (int g2 = 0; g2 < 4; g2++) {
                const uint32_t off = (uint32_t)((g2 * 16 + laneRowB) * AP + kv * 16 + laneColB) * 2;
                LDSM_X4(vbh[g2][0], vbh[g2][1], vbh[g2][2], vbh[g2][3], Vhs + off);
                LDSM_X4(vbl[g2][0], vbl[g2][1], vbl[g2][2], vbl[g2][3], Vls + off);
            }
#pragma unroll
            for (int df = 0; df < 8; df++) {
                const int g2 = df >> 1, hb = (df & 1) * 2;
                float* a4 = sO[df];
                MMA_BF16(a4[0], a4[1], a4[2], a4[3],
                         aPh[0], aPh[1], aPh[2], aPh[3],
                         vbh[g2][hb], vbh[g2][hb + 1]);
                MMA_BF16(a4[0], a4[1], a4[2], a4[3],
                         aPh[0], aPh[1], aPh[2], aPh[3],
                         vbl[g2][hb], vbl[g2][hb + 1]);
                MMA_BF16(a4[0], a4[1], a4[2], a4[3],
                         aPl[0], aPl[1], aPl[2], aPl[3],
                         vbh[g2][hb], vbh[g2][hb + 1]);
            }
        }
    }

    l0 += __shfl_xor_sync(0xffffffffu, l0, 1);
    l0 += __shfl_xor_sync(0xffffffffu, l0, 2);
    l1 += __shfl_xor_sync(0xffffffffu, l1, 1);
    l1 += __shfl_xor_sync(0xffffffffu, l1, 2);
    const float sc0 = ((l0 > 0.f) ? (1.f / l0) : 0.f) * q_mask[(size_t)b * LSEQ + qrow0];
    const float sc1 = ((l1 > 0.f) ? (1.f / l1) : 0.f) * q_mask[(size_t)b * LSEQ + qrow1];
#pragma unroll
    for (int df = 0; df < 8; df++) {
        const int d = df * 8 + 2 * (l & 3);
        float2 o0; o0.x = sO[df][0] * sc0; o0.y = sO[df][1] * sc0;
        float2 o1; o1.x = sO[df][2] * sc1; o1.y = sO[df][3] * sc1;
        *(float2*)&out[((size_t)b * LSEQ + qrow0) * DMODEL + h * 64 + d] = o0;
        *(float2*)&out[((size_t)b * LSEQ + qrow1) * DMODEL + h * 64 + d] = o1;
    }
}

// --------- fallback: rows q >= kmax -> uniform mean over penalty==-1e10 set ----
__global__ void fallback_kernel(const float* __restrict__ v_mask,
                                const float* __restrict__ q_mask,
                                float* __restrict__ out)
{
    const int b   = blockIdx.x;
    const int dim = blockIdx.y * blockDim.x + threadIdx.x;
    const int   kmax = g_kmax[b];
    const float cnt1 = g_cnt[b];
    const float* vw = g_vw + (size_t)b * LSEQ * DMODEL;

    float s1 = 0.f;
    for (int k = 0; k < LSEQ; k++)
        s1 += v_mask[(size_t)b * LSEQ + k] * vw[(size_t)k * DMODEL + dim];

    float suff = 0.f;
    for (int q = LSEQ - 1; q >= kmax; q--) {
        const float denom = cnt1 + (float)(LSEQ - 1 - q);
        const float val = (denom > 0.f) ? (s1 + suff) / denom : 0.f;
        out[((size_t)b * LSEQ + q) * DMODEL + dim] = val * q_mask[(size_t)b * LSEQ + q];
        suff += vw[(size_t)q * DMODEL + dim];
    }
}

// -------------------------------- launch ---------------------------------------
extern "C" void kernel_launch(void* const* d_in, const int* in_sizes, int n_in,
                              void* d_out, int out_size)
{
    const float* q      = (const float*)d_in[0];
    const float* k      = (const float*)d_in[1];
    const float* v      = (const float*)d_in[2];
    const float* v_mask = (const float*)d_in[3];
    const float* q_mask = (const float*)d_in[4];
    const float* Wq     = (const float*)d_in[5];
    const float* Wk     = (const float*)d_in[6];
    const float* Wv     = (const float*)d_in[7];
    float* out = (float*)d_out;

    cudaFuncSetAttribute(gemm_kernel, cudaFuncAttributeMaxDynamicSharedMemorySize, GEMM_SMEM);
    cudaFuncSetAttribute(attn_kernel, cudaFuncAttributeMaxDynamicSharedMemorySize, ATTN_SMEM);

    const int nblk = XBLK + (WSZ / 4) / 256;   // 5120
    split2_kernel<<<nblk, 256>>>(q, Wq, 0);
    split2_kernel<<<nblk, 256>>>(k, Wk, 1);
    split2_kernel<<<nblk, 256>>>(v, Wv, 2);

    dim3 gg(DMODEL / 128, MROWS / 128, 3);
    gemm_kernel<<<gg, 256, GEMM_SMEM>>>();

    mask_stats_kernel<<<BATCH, 256>>>(v_mask);

    dim3 ag(NQT, NHEADS, BATCH);
    attn_kernel<<<ag, 256, ATTN_SMEM>>>(v_mask, q_mask, out);

    fallback_kernel<<<dim3(BATCH, DMODEL / 128), 128>>>(v_mask, q_mask, out);
}

// round 15
// speedup vs baseline: 1.0011x; 1.0011x over previous
#include <cuda_runtime.h>
#include <cuda_bf16.h>
#include <math.h>
#include <stdint.h>

#define BATCH   2
#define LSEQ    2048
#define DMODEL  1024
#define NHEADS  16
#define DHEAD   64
#define NKT     (LSEQ / 64)
#define NQT     (LSEQ / 128)

#define MROWS   (BATCH * LSEQ)      // 4096
#define XSZ     (MROWS * DMODEL)    // 4194304
#define WSZ     (DMODEL * DMODEL)   // 1048576

// ---------------- scratch (allocation-free: __device__ globals) ----------------
__device__ float g_vw[XSZ];
__device__ int   g_kmax[BATCH];
__device__ float g_cnt[BATCH];
__device__ __nv_bfloat16 g_xh[3 * XSZ];
__device__ __nv_bfloat16 g_xl[3 * XSZ];
__device__ __nv_bfloat16 g_wh[3 * WSZ];
__device__ __nv_bfloat16 g_wl[3 * WSZ];
__device__ __nv_bfloat16 g_qsh[XSZ], g_qsl[XSZ];  // Q proj (pre-scaled by CSC), hi/lo
__device__ __nv_bfloat16 g_ksh[XSZ], g_ksl[XSZ];  // K proj, hi/lo
__device__ __nv_bfloat16 g_vth[XSZ], g_vtl[XSZ];  // V proj transposed, hi/lo

// ============================ PTX helpers (portable sm_80+) ====================
__device__ __forceinline__ uint32_t smem_u32(const void* p) {
    uint32_t a;
    asm("{ .reg .u64 t; cvta.to.shared.u64 t, %1; cvt.u32.u64 %0, t; }" : "=r"(a) : "l"(p));
    return a;
}
#define CP_ASYNC16(dst, src) \
    asm volatile("cp.async.cg.shared.global [%0], [%1], 16;" :: "r"(dst), "l"(src) : "memory")
#define CP_COMMIT() asm volatile("cp.async.commit_group;" ::: "memory")
#define CP_WAIT1()  asm volatile("cp.async.wait_group 1;" ::: "memory")
#define CP_WAIT0()  asm volatile("cp.async.wait_group 0;" ::: "memory")

#define LDSM_X4(R0, R1, R2, R3, ADDR) \
    asm volatile("ldmatrix.sync.aligned.m8n8.x4.shared.b16 {%0,%1,%2,%3}, [%4];" \
                 : "=r"(R0), "=r"(R1), "=r"(R2), "=r"(R3) : "r"(ADDR))

#define MMA_BF16(C0, C1, C2, C3, A0, A1, A2, A3, B0, B1) \
    asm volatile("mma.sync.aligned.m16n8k16.row.col.f32.bf16.bf16.f32 " \
                 "{%0,%1,%2,%3}, {%4,%5,%6,%7}, {%8,%9}, {%0,%1,%2,%3};" \
                 : "+f"(C0), "+f"(C1), "+f"(C2), "+f"(C3) \
                 : "r"(A0), "r"(A1), "r"(A2), "r"(A3), "r"(B0), "r"(B1))

#define PACK_BF16X2(R, A, B) \
    asm("cvt.rn.bf16x2.f32 %0, %1, %2;" : "=r"(R) : "f"(B), "f"(A))

// fast 2^x, no clamp. FMA pipes only. rel err ~2.4e-6.
__device__ __forceinline__ float fexp2nc(float x) {
    float t = x + 12582912.f;
    float n = t - 12582912.f;
    float f = x - n;
    float p = 1.3333558e-3f;
    p = fmaf(p, f, 9.6181291e-3f);
    p = fmaf(p, f, 5.5504109e-2f);
    p = fmaf(p, f, 2.4022651e-1f);
    p = fmaf(p, f, 6.9314718e-1f);
    p = fmaf(p, f, 1.0f);
    int sc = (__float_as_int(t) + (127 - 0x4B400000)) << 23;
    return p * __int_as_float(sc);
}

__device__ __forceinline__ void split1(float x, __nv_bfloat16& h, __nv_bfloat16& l) {
    h = __float2bfloat16_rn(x);
    l = __float2bfloat16_rn(x - __bfloat162float(h));
}
__device__ __forceinline__ void packsplit2(float a, float b, uint32_t& hi, uint32_t& lo) {
    PACK_BF16X2(hi, a, b);
    float ra = __uint_as_float(hi << 16);
    float rb = __uint_as_float(hi & 0xFFFF0000u);
    PACK_BF16X2(lo, a - ra, b - rb);
}

#define CSC 0.18033688f   /* 0.125 * log2(e), folded into Q at projection */

// ================= fp32 -> bf16 hi/lo split (x and W in one launch) ============
#define XBLK (XSZ / 4 / 256)
__global__ void split2_kernel(const float* __restrict__ xs,
                              const float* __restrict__ ws, int sel)
{
    const int blk = blockIdx.x;
    const float* src;
    __nv_bfloat16* hi;
    __nv_bfloat16* lo;
    int i;
    if (blk < XBLK) {
        i = blk * 256 + threadIdx.x;
        src = xs;
        hi = g_xh + (size_t)sel * XSZ; lo = g_xl + (size_t)sel * XSZ;
    } else {
        i = (blk - XBLK) * 256 + threadIdx.x;
        src = ws;
        hi = g_wh + (size_t)sel * WSZ; lo = g_wl + (size_t)sel * WSZ;
    }
    float4 x = ((const float4*)src)[i];
    __nv_bfloat162 h01, h23, l01, l23;
    split1(x.x, h01.x, l01.x); split1(x.y, h01.y, l01.y);
    split1(x.z, h23.x, l23.x); split1(x.w, h23.y, l23.y);
    ((__nv_bfloat162*)hi)[2 * i]     = h01;
    ((__nv_bfloat162*)hi)[2 * i + 1] = h23;
    ((__nv_bfloat162*)lo)[2 * i]     = l01;
    ((__nv_bfloat162*)lo)[2 * i + 1] = l23;
}

// ====== mma.sync projection GEMM: CTA 128x256, warp tile 64x64 (best: 241us) ===
#define GK        64
#define GPAD      72
#define NCHUNK    (DMODEL / GK)
#define BUFA      (128 * GPAD)
#define BUFB      (256 * GPAD)
#define STAGE_ELEMS (2 * BUFA + 2 * BUFB)
#define GEMM_SMEM (2 * STAGE_ELEMS * 2)

__global__ __launch_bounds__(256, 1) void gemm_kernel()
{
    extern __shared__ __nv_bfloat16 gsm[];
    const int sel = blockIdx.z;
    const int n0  = blockIdx.x * 256;
    const int m0  = blockIdx.y * 128;
    const int t   = threadIdx.x;
    const int w   = t >> 5, l = t & 31;

    const __nv_bfloat16* __restrict__ Ah = g_xh + (size_t)sel * XSZ;
    const __nv_bfloat16* __restrict__ Al = g_xl + (size_t)sel * XSZ;
    const __nv_bfloat16* __restrict__ Bh = g_wh + (size_t)sel * WSZ;
    const __nv_bfloat16* __restrict__ Bl = g_wl + (size_t)sel * WSZ;

    auto issue = [&](int c, int s) {
        __nv_bfloat16* base = gsm + s * STAGE_ELEMS;
        const int k0 = c * GK;
#pragma unroll
        for (int i = 0; i < 8; i++) {
            const int cid = t + i * 256;
            const int buf = cid >> 10;
            const int row = (cid >> 3) & 127;
            const int seg = cid & 7;
            const __nv_bfloat16* src = (buf ? Al : Ah) + (size_t)(m0 + row) * DMODEL + k0 + seg * 8;
            CP_ASYNC16(smem_u32(base + buf * BUFA + row * GPAD + seg * 8), src);
        }
#pragma unroll
        for (int i = 0; i < 16; i++) {
            const int cid = t + i * 256;
            const int buf = cid >> 11;
            const int row = (cid >> 3) & 255;
            const int seg = cid & 7;
            const __nv_bfloat16* src = (buf ? Bl : Bh) + (size_t)(n0 + row) * DMODEL + k0 + seg * 8;
            CP_ASYNC16(smem_u32(base + 2 * BUFA + buf * BUFB + row * GPAD + seg * 8), src);
        }
        CP_COMMIT();
    };

    const int wm = (w >> 2) * 64;
    const int wn = (w & 3) * 64;
    const int laneRowA = l & 15;
    const int laneColA = (l >> 4) * 8;
    const int laneRowB = (l >> 4) * 8 + (l & 7);
    const int laneColB = ((l >> 3) & 1) * 8;

    float acc[4][8][4];
#pragma unroll
    for (int mf = 0; mf < 4; mf++)
#pragma unroll
        for (int nf = 0; nf < 8; nf++)
#pragma unroll
            for (int i = 0; i < 4; i++) acc[mf][nf][i] = 0.f;

    issue(0, 0);

    for (int c = 0; c < NCHUNK; c++) {
        if (c + 1 < NCHUNK) { issue(c + 1, (c + 1) & 1); CP_WAIT1(); }
        else                { CP_WAIT0(); }
        __syncthreads();

        const uint32_t stage = smem_u32(gsm) + (uint32_t)((c & 1) * STAGE_ELEMS) * 2;
        const uint32_t xh0 = stage;
        const uint32_t xl0 = stage + BUFA * 2;
        const uint32_t wh0 = stage + 2 * BUFA * 2;
        const uint32_t wl0 = stage + 2 * BUFA * 2 + BUFB * 2;

#pragma unroll
        for (int ks = 0; ks < 4; ks++) {
            const int kc = ks * 16;
            uint32_t ah[4][4], al[4][4];
#pragma unroll
            for (int mf = 0; mf < 4; mf++) {
                const uint32_t off = (uint32_t)((wm + mf * 16 + laneRowA) * GPAD + kc + laneColA) * 2;
                LDSM_X4(ah[mf][0], ah[mf][1], ah[mf][2], ah[mf][3], xh0 + off);
                LDSM_X4(al[mf][0], al[mf][1], al[mf][2], al[mf][3], xl0 + off);
            }
#pragma unroll
            for (int half = 0; half < 2; half++) {
                uint32_t bh[2][4], bl[2][4];
#pragma unroll
                for (int gg = 0; gg < 2; gg++) {
                    const int g2 = half * 2 + gg;
                    const uint32_t off = (uint32_t)((wn + g2 * 16 + laneRowB) * GPAD + kc + laneColB) * 2;
                    LDSM_X4(bh[gg][0], bh[gg][1], bh[gg][2], bh[gg][3], wh0 + off);
                    LDSM_X4(bl[gg][0], bl[gg][1], bl[gg][2], bl[gg][3], wl0 + off);
                }
#pragma unroll
                for (int mf = 0; mf < 4; mf++) {
#pragma unroll
                    for (int nfl = 0; nfl < 4; nfl++) {
                        const int nf = half * 4 + nfl;
                        const int gg = nfl >> 1, hb = (nfl & 1) * 2;
                        float* a4 = acc[mf][nf];
                        MMA_BF16(a4[0], a4[1], a4[2], a4[3],
                                 ah[mf][0], ah[mf][1], ah[mf][2], ah[mf][3],
                                 bh[gg][hb], bh[gg][hb + 1]);
                        MMA_BF16(a4[0], a4[1], a4[2], a4[3],
                                 ah[mf][0], ah[mf][1], ah[mf][2], ah[mf][3],
                                 bl[gg][hb], bl[gg][hb + 1]);
                        MMA_BF16(a4[0], a4[1], a4[2], a4[3],
                                 al[mf][0], al[mf][1], al[mf][2], al[mf][3],
                                 bh[gg][hb], bh[gg][hb + 1]);
                    }
                }
            }
        }
        __syncthreads();
    }

    const int cr = l >> 2;
    const int cc = (l & 3) * 2;
#pragma unroll
    for (int mf = 0; mf < 4; mf++) {
#pragma unroll
        for (int nf = 0; nf < 8; nf++) {
            const int row = m0 + wm + mf * 16 + cr;
            const int col = n0 + wn + nf * 8 + cc;
            float a0 = acc[mf][nf][0], a1 = acc[mf][nf][1];
            float a2 = acc[mf][nf][2], a3 = acc[mf][nf][3];
            if (sel == 2) {
                float2 v0; v0.x = a0; v0.y = a1;
                float2 v1; v1.x = a2; v1.y = a3;
                *(float2*)&g_vw[(size_t)row * DMODEL + col]       = v0;
                *(float2*)&g_vw[(size_t)(row + 8) * DMODEL + col] = v1;
                const int b = row >> 11, sq = row & 2047;
                const int hh = col >> 6, dd = col & 63;
                const size_t tb = (size_t)(b * NHEADS + hh) * 64;
                __nv_bfloat16 h, lo2;
                split1(a0, h, lo2);
                g_vth[(tb + dd) * LSEQ + sq] = h;     g_vtl[(tb + dd) * LSEQ + sq] = lo2;
                split1(a1, h, lo2);
                g_vth[(tb + dd + 1) * LSEQ + sq] = h; g_vtl[(tb + dd + 1) * LSEQ + sq] = lo2;
                split1(a2, h, lo2);
                g_vth[(tb + dd) * LSEQ + sq + 8] = h; g_vtl[(tb + dd) * LSEQ + sq + 8] = lo2;
                split1(a3, h, lo2);
                g_vth[(tb + dd + 1) * LSEQ + sq + 8] = h; g_vtl[(tb + dd + 1) * LSEQ + sq + 8] = lo2;
            } else {
                __nv_bfloat16* H;
                __nv_bfloat16* L;
                if (sel == 1) { H = g_ksh; L = g_ksl; }
                else {
                    H = g_qsh; L = g_qsl;
                    a0 *= CSC; a1 *= CSC; a2 *= CSC; a3 *= CSC;
                }
                __nv_bfloat162 h0, l0, h1, l1;
                split1(a0, h0.x, l0.x); split1(a1, h0.y, l0.y);
                split1(a2, h1.x, l1.x); split1(a3, h1.y, l1.y);
                *(__nv_bfloat162*)&H[(size_t)row * DMODEL + col]       = h0;
                *(__nv_bfloat162*)&L[(size_t)row * DMODEL + col]       = l0;
                *(__nv_bfloat162*)&H[(size_t)(row + 8) * DMODEL + col] = h1;
                *(__nv_bfloat162*)&L[(size_t)(row + 8) * DMODEL + col] = l1;
            }
        }
    }
}

// ---------------- per-batch mask stats ----------------------------------------
__global__ void mask_stats_kernel(const float* __restrict__ v_mask)
{
    const int b = blockIdx.x;
    const int t = threadIdx.x;
    __shared__ int   smax[256];
    __shared__ float scnt[256];
    int   km = -1;
    float c  = 0.f;
    for (int k = t; k < LSEQ; k += 256) {
        if (v_mask[(size_t)b * LSEQ + k] != 0.f) { km = k; c += 1.f; }
    }
    smax[t] = km; scnt[t] = c;
    __syncthreads();
    for (int s = 128; s > 0; s >>= 1) {
        if (t < s) {
            smax[t] = max(smax[t], smax[t + s]);
            scnt[t] += scnt[t + s];
        }
        __syncthreads();
    }
    if (t == 0) {
        g_kmax[b] = (smax[0] < 0) ? 0 : smax[0];
        g_cnt[b]  = scnt[0];
    }
}

// ========= tensor-core flash attention: q-tile 128, 2 CTAs/SM ==================
// __launch_bounds__(256,2): 4 warps/SMSP so softmax (fma pipe) of one CTA
// overlaps MMA (tensor pipe) of the other. smem 111KB x2 = 222KB <= 227KB.
#define AP 72
#define KVBUF (64 * AP)
#define NKVB  4
#define ATTN_SMEM ((2 * 128 * AP + 2 * NKVB * KVBUF) * 2 + 2 * 64 * 4)

__global__ __launch_bounds__(256, 2) void attn_kernel(const float* __restrict__ v_mask,
                                                      const float* __restrict__ q_mask,
                                                      float* __restrict__ out)
{
    extern __shared__ __nv_bfloat16 ash[];
    __nv_bfloat16* Qh = ash;
    __nv_bfloat16* Ql = Qh + 128 * AP;
    __nv_bfloat16* KV = Ql + 128 * AP;
    float* vms = (float*)(KV + 2 * NKVB * KVBUF);

    const int qt = blockIdx.x, h = blockIdx.y, b = blockIdx.z;
    const int t = threadIdx.x, w = t >> 5, l = t & 31;

    const size_t kbase  = (size_t)b * LSEQ * DMODEL + h * 64;
    const size_t vtbase = (size_t)(b * NHEADS + h) * 64 * LSEQ;
    const size_t vmbase = (size_t)b * LSEQ;

    auto issueKV = [&](int kt, int st) {
#pragma unroll
        for (int i = 0; i < 8; i++) {
            const int cid = t + i * 256;
            const int buf = cid >> 9;
            const int row = (cid >> 3) & 63;
            const int s8  = cid & 7;
            const __nv_bfloat16* src;
            if      (buf == 0) src = g_ksh + kbase + (size_t)(kt * 64 + row) * DMODEL + s8 * 8;
            else if (buf == 1) src = g_ksl + kbase + (size_t)(kt * 64 + row) * DMODEL + s8 * 8;
            else if (buf == 2) src = g_vth + vtbase + (size_t)row * LSEQ + kt * 64 + s8 * 8;
            else               src = g_vtl + vtbase + (size_t)row * LSEQ + kt * 64 + s8 * 8;
            CP_ASYNC16(smem_u32(KV + ((size_t)(st * NKVB + buf)) * KVBUF + row * AP + s8 * 8), src);
        }
        if (t < 16)
            CP_ASYNC16(smem_u32(vms + st * 64 + t * 4), v_mask + vmbase + kt * 64 + t * 4);
        CP_COMMIT();
    };

    {
#pragma unroll
        for (int i = 0; i < 8; i++) {
            const int cid = t + i * 256;
            const int hl  = cid >> 10;
            const int row = (cid >> 3) & 127;
            const int s8  = cid & 7;
            const size_t goff = ((size_t)(b * LSEQ + qt * 128 + row)) * DMODEL + h * 64 + s8 * 8;
            const __nv_bfloat16* src = hl ? (g_qsl + goff) : (g_qsh + goff);
            __nv_bfloat16* dst = hl ? (Ql + row * AP + s8 * 8) : (Qh + row * AP + s8 * 8);
            CP_ASYNC16(smem_u32(dst), src);
        }
        CP_COMMIT();
    }

    const int kt0 = qt * 2;
    issueKV(kt0, 0);
    CP_WAIT0();
    __syncthreads();

    const int laneRowA = l & 15;
    const int laneColA = (l >> 4) * 8;
    const int laneRowB = (l >> 4) * 8 + (l & 7);
    const int laneColB = ((l >> 3) & 1) * 8;

    uint32_t aQh[4][4], aQl[4][4];
#pragma unroll
    for (int ks = 0; ks < 4; ks++) {
        const uint32_t off = (uint32_t)((w * 16 + laneRowA) * AP + ks * 16 + laneColA) * 2;
        LDSM_X4(aQh[ks][0], aQh[ks][1], aQh[ks][2], aQh[ks][3], smem_u32(Qh) + off);
        LDSM_X4(aQl[ks][0], aQl[ks][1], aQl[ks][2], aQl[ks][3], smem_u32(Ql) + off);
    }

    float sO[8][4];
#pragma unroll
    for (int df = 0; df < 8; df++)
#pragma unroll
        for (int i = 0; i < 4; i++) sO[df][i] = 0.f;
    float l0 = 0.f, l1 = 0.f;

    const int qrow0 = qt * 128 + w * 16 + (l >> 2);
    const int qrow1 = qrow0 + 8;

    for (int kt = kt0; kt < NKT; kt++) {
        const int st = (kt - kt0) & 1;
        if (kt > kt0) { CP_WAIT0(); }
        __syncthreads();
        if (kt + 1 < NKT) issueKV(kt + 1, st ^ 1);

        const uint32_t Khs = smem_u32(KV + (size_t)(st * NKVB + 0) * KVBUF);
        const uint32_t Kls = smem_u32(KV + (size_t)(st * NKVB + 1) * KVBUF);
        const uint32_t Vhs = smem_u32(KV + (size_t)(st * NKVB + 2) * KVBUF);
        const uint32_t Vls = smem_u32(KV + (size_t)(st * NKVB + 3) * KVBUF);
        const float* vmsb = vms + st * 64;

        float s[8][4];
#pragma unroll
        for (int nf = 0; nf < 8; nf++)
#pragma unroll
            for (int i = 0; i < 4; i++) s[nf][i] = 0.f;
#pragma unroll
        for (int ks = 0; ks < 4; ks++) {
            uint32_t kbh[4][4], kbl[4][4];
#pragma unroll
            for (int g2 = 0; g2 < 4; g2++) {
                const uint32_t off = (uint32_t)((g2 * 16 + laneRowB) * AP + ks * 16 + laneColB) * 2;
                LDSM_X4(kbh[g2][0], kbh[g2][1], kbh[g2][2], kbh[g2][3], Khs + off);
                LDSM_X4(kbl[g2][0], kbl[g2][1], kbl[g2][2], kbl[g2][3], Kls + off);
            }
#pragma unroll
            for (int nf = 0; nf < 8; nf++) {
                const int g2 = nf >> 1, hb = (nf & 1) * 2;
                float* a4 = s[nf];
                MMA_BF16(a4[0], a4[1], a4[2], a4[3],
                         aQh[ks][0], aQh[ks][1], aQh[ks][2], aQh[ks][3],
                         kbh[g2][hb], kbh[g2][hb + 1]);
                MMA_BF16(a4[0], a4[1], a4[2], a4[3],
                         aQh[ks][0], aQh[ks][1], aQh[ks][2], aQh[ks][3],
                         kbl[g2][hb], kbl[g2][hb + 1]);
                MMA_BF16(a4[0], a4[1], a4[2], a4[3],
                         aQl[ks][0], aQl[ks][1], aQl[ks][2], aQl[ks][3],
                         kbh[g2][hb], kbh[g2][hb + 1]);
            }
        }

        if (kt <= kt0 + 1) {
#pragma unroll
            for (int nf = 0; nf < 8; nf++) {
                const int cl0 = nf * 8 + 2 * (l & 3);
                const float vm0 = vmsb[cl0], vm1 = vmsb[cl0 + 1];
                const int c0 = kt * 64 + cl0, c1 = c0 + 1;
                const float m00 = (c0 > qrow0) ? vm0 : 0.f;
                const float m10 = (c1 > qrow0) ? vm1 : 0.f;
                const float m01 = (c0 > qrow1) ? vm0 : 0.f;
                const float m11 = (c1 > qrow1) ? vm1 : 0.f;
                float p0 = fexp2nc(s[nf][0]) * m00;
                float p1 = fexp2nc(s[nf][1]) * m10;
                float p2 = fexp2nc(s[nf][2]) * m01;
                float p3 = fexp2nc(s[nf][3]) * m11;
                l0 += p0 + p1;
                l1 += p2 + p3;
                s[nf][0] = p0; s[nf][1] = p1; s[nf][2] = p2; s[nf][3] = p3;
            }
        } else {
#pragma unroll
            for (int nf = 0; nf < 8; nf++) {
                const int cl0 = nf * 8 + 2 * (l & 3);
                const float vm0 = vmsb[cl0], vm1 = vmsb[cl0 + 1];
                float p0 = fexp2nc(s[nf][0]) * vm0;
                float p1 = fexp2nc(s[nf][1]) * vm1;
                float p2 = fexp2nc(s[nf][2]) * vm0;
                float p3 = fexp2nc(s[nf][3]) * vm1;
                l0 += p0 + p1;
                l1 += p2 + p3;
                s[nf][0] = p0; s[nf][1] = p1; s[nf][2] = p2; s[nf][3] = p3;
            }
        }

#pragma unroll
        for (int kv = 0; kv < 4; kv++) {
            uint32_t aPh[4], aPl[4];
            packsplit2(s[2 * kv][0],     s[2 * kv][1],     aPh[0], aPl[0]);
            packsplit2(s[2 * kv][2],     s[2 * kv][3],     aPh[1], aPl[1]);
            packsplit2(s[2 * kv + 1][0], s[2 * kv + 1][1], aPh[2], aPl[2]);
            packsplit2(s[2 * kv + 1][2], s[2 * kv + 1][3], aPh[3], aPl[3]);
            uint32_t vbh[4][4], vbl[4][4];
#pragma unroll
            for (int g2 = 0; g2 < 4; g2++) {
                const uint32_t off = (uint32_t)((g2 * 16 + laneRowB) * AP + kv * 16 + laneColB) * 2;
                LDSM_X4(vbh[g2][0], vbh[g2][1], vbh[g2][2], vbh[g2][3], Vhs + off);
                LDSM_X4(vbl[g2][0], vbl[g2][1], vbl[g2][2], vbl[g2][3], Vls + off);
            }
#pragma unroll
            for (int df = 0; df < 8; df++) {
                const int g2 = df >> 1, hb = (df & 1) * 2;
                float* a4 = sO[df];
                MMA_BF16(a4[0], a4[1], a4[2], a4[3],
                         aPh[0], aPh[1], aPh[2], aPh[3],
                         vbh[g2][hb], vbh[g2][hb + 1]);
                MMA_BF16(a4[0], a4[1], a4[2], a4[3],
                         aPh[0], aPh[1], aPh[2], aPh[3],
                         vbl[g2][hb], vbl[g2][hb + 1]);
                MMA_BF16(a4[0], a4[1], a4[2], a4[3],
                         aPl[0], aPl[1], aPl[2], aPl[3],
                         vbh[g2][hb], vbh[g2][hb + 1]);
            }
        }
    }

    l0 += __shfl_xor_sync(0xffffffffu, l0, 1);
    l0 += __shfl_xor_sync(0xffffffffu, l0, 2);
    l1 += __shfl_xor_sync(0xffffffffu, l1, 1);
    l1 += __shfl_xor_sync(0xffffffffu, l1, 2);
    const float sc0 = ((l0 > 0.f) ? (1.f / l0) : 0.f) * q_mask[(size_t)b * LSEQ + qrow0];
    const float sc1 = ((l1 > 0.f) ? (1.f / l1) : 0.f) * q_mask[(size_t)b * LSEQ + qrow1];
#pragma unroll
    for (int df = 0; df < 8; df++) {
        const int d = df * 8 + 2 * (l & 3);
        float2 o0; o0.x = sO[df][0] * sc0; o0.y = sO[df][1] * sc0;
        float2 o1; o1.x = sO[df][2] * sc1; o1.y = sO[df][3] * sc1;
        *(float2*)&out[((size_t)b * LSEQ + qrow0) * DMODEL + h * 64 + d] = o0;
        *(float2*)&out[((size_t)b * LSEQ + qrow1) * DMODEL + h * 64 + d] = o1;
    }
}

// --------- fallback: rows q >= kmax -> uniform mean over penalty==-1e10 set ----
__global__ void fallback_kernel(const float* __restrict__ v_mask,
                                const float* __restrict__ q_mask,
                                float* __restrict__ out)
{
    const int b   = blockIdx.x;
    const int dim = blockIdx.y * blockDim.x + threadIdx.x;
    const int   kmax = g_kmax[b];
    const float cnt1 = g_cnt[b];
    const float* vw = g_vw + (size_t)b * LSEQ * DMODEL;

    float s1 = 0.f;
    for (int k = 0; k < LSEQ; k++)
        s1 += v_mask[(size_t)b * LSEQ + k] * vw[(size_t)k * DMODEL + dim];

    float suff = 0.f;
    for (int q = LSEQ - 1; q >= kmax; q--) {
        const float denom = cnt1 + (float)(LSEQ - 1 - q);
        const float val = (denom > 0.f) ? (s1 + suff) / denom : 0.f;
        out[((size_t)b * LSEQ + q) * DMODEL + dim] = val * q_mask[(size_t)b * LSEQ + q];
        suff += vw[(size_t)q * DMODEL + dim];
    }
}

// -------------------------------- launch ---------------------------------------
extern "C" void kernel_launch(void* const* d_in, const int* in_sizes, int n_in,
                              void* d_out, int out_size)
{
    const float* q      = (const float*)d_in[0];
    const float* k      = (const float*)d_in[1];
    const float* v      = (const float*)d_in[2];
    const float* v_mask = (const float*)d_in[3];
    const float* q_mask = (const float*)d_in[4];
    const float* Wq     = (const float*)d_in[5];
    const float* Wk     = (const float*)d_in[6];
    const float* Wv     = (const float*)d_in[7];
    float* out = (float*)d_out;

    cudaFuncSetAttribute(gemm_kernel, cudaFuncAttributeMaxDynamicSharedMemorySize, GEMM_SMEM);
    cudaFuncSetAttribute(attn_kernel, cudaFuncAttributeMaxDynamicSharedMemorySize, ATTN_SMEM);

    const int nblk = XBLK + (WSZ / 4) / 256;
    split2_kernel<<<nblk, 256>>>(q, Wq, 0);
    split2_kernel<<<nblk, 256>>>(k, Wk, 1);
    split2_kernel<<<nblk, 256>>>(v, Wv, 2);

    dim3 gg(DMODEL / 256, MROWS / 128, 3);
    gemm_kernel<<<gg, 256, GEMM_SMEM>>>();

    mask_stats_kernel<<<BATCH, 256>>>(v_mask);

    dim3 ag(NQT, NHEADS, BATCH);
    attn_kernel<<<ag, 256, ATTN_SMEM>>>(v_mask, q_mask, out);

    fallback_kernel<<<dim3(BATCH, DMODEL / 128), 128>>>(v_mask, q_mask, out);
}

// round 16
// speedup vs baseline: 1.0345x; 1.0333x over previous
#include <cuda_runtime.h>
#include <cuda_bf16.h>
#include <math.h>
#include <stdint.h>

#define BATCH   2
#define LSEQ    2048
#define DMODEL  1024
#define NHEADS  16
#define DHEAD   64
#define NKT     (LSEQ / 64)
#define NQT     (LSEQ / 128)

#define MROWS   (BATCH * LSEQ)      // 4096
#define XSZ     (MROWS * DMODEL)    // 4194304
#define WSZ     (DMODEL * DMODEL)   // 1048576

// ---------------- scratch (allocation-free: __device__ globals) ----------------
__device__ float g_vw[XSZ];
__device__ int   g_kmax[BATCH];
__device__ float g_cnt[BATCH];
__device__ __nv_bfloat16 g_xh[3 * XSZ];
__device__ __nv_bfloat16 g_xl[3 * XSZ];
__device__ __nv_bfloat16 g_wh[3 * WSZ];
__device__ __nv_bfloat16 g_wl[3 * WSZ];
__device__ __nv_bfloat16 g_qsh[XSZ], g_qsl[XSZ];  // Q proj (pre-scaled by CSC), hi/lo
__device__ __nv_bfloat16 g_ksh[XSZ], g_ksl[XSZ];  // K proj, hi/lo
__device__ __nv_bfloat16 g_vth[XSZ], g_vtl[XSZ];  // V proj transposed, hi/lo

// ============================ PTX helpers (portable sm_80+) ====================
__device__ __forceinline__ uint32_t smem_u32(const void* p) {
    uint32_t a;
    asm("{ .reg .u64 t; cvta.to.shared.u64 t, %1; cvt.u32.u64 %0, t; }" : "=r"(a) : "l"(p));
    return a;
}
#define CP_ASYNC16(dst, src) \
    asm volatile("cp.async.cg.shared.global [%0], [%1], 16;" :: "r"(dst), "l"(src) : "memory")
#define CP_COMMIT() asm volatile("cp.async.commit_group;" ::: "memory")
#define CP_WAIT1()  asm volatile("cp.async.wait_group 1;" ::: "memory")
#define CP_WAIT0()  asm volatile("cp.async.wait_group 0;" ::: "memory")

#define LDSM_X4(R0, R1, R2, R3, ADDR) \
    asm volatile("ldmatrix.sync.aligned.m8n8.x4.shared.b16 {%0,%1,%2,%3}, [%4];" \
                 : "=r"(R0), "=r"(R1), "=r"(R2), "=r"(R3) : "r"(ADDR))

#define MMA_BF16(C0, C1, C2, C3, A0, A1, A2, A3, B0, B1) \
    asm volatile("mma.sync.aligned.m16n8k16.row.col.f32.bf16.bf16.f32 " \
                 "{%0,%1,%2,%3}, {%4,%5,%6,%7}, {%8,%9}, {%0,%1,%2,%3};" \
                 : "+f"(C0), "+f"(C1), "+f"(C2), "+f"(C3) \
                 : "r"(A0), "r"(A1), "r"(A2), "r"(A3), "r"(B0), "r"(B1))

#define PACK_BF16X2(R, A, B) \
    asm("cvt.rn.bf16x2.f32 %0, %1, %2;" : "=r"(R) : "f"(B), "f"(A))

// fast 2^x, no clamp. FMA pipes only. rel err ~2.4e-6.
__device__ __forceinline__ float fexp2nc(float x) {
    float t = x + 12582912.f;
    float n = t - 12582912.f;
    float f = x - n;
    float p = 1.3333558e-3f;
    p = fmaf(p, f, 9.6181291e-3f);
    p = fmaf(p, f, 5.5504109e-2f);
    p = fmaf(p, f, 2.4022651e-1f);
    p = fmaf(p, f, 6.9314718e-1f);
    p = fmaf(p, f, 1.0f);
    int sc = (__float_as_int(t) + (127 - 0x4B400000)) << 23;
    return p * __int_as_float(sc);
}

__device__ __forceinline__ void split1(float x, __nv_bfloat16& h, __nv_bfloat16& l) {
    h = __float2bfloat16_rn(x);
    l = __float2bfloat16_rn(x - __bfloat162float(h));
}
__device__ __forceinline__ void packsplit2(float a, float b, uint32_t& hi, uint32_t& lo) {
    PACK_BF16X2(hi, a, b);
    float ra = __uint_as_float(hi << 16);
    float rb = __uint_as_float(hi & 0xFFFF0000u);
    PACK_BF16X2(lo, a - ra, b - rb);
}

#define CSC 0.18033688f   /* 0.125 * log2(e), folded into Q at projection */

// ========== fp32 -> bf16 hi/lo split, all three tensors in ONE launch ==========
#define XBLK (XSZ / 4 / 256)
#define WBLK (WSZ / 4 / 256)
__global__ void split3_kernel(const float* __restrict__ q, const float* __restrict__ k,
                              const float* __restrict__ v, const float* __restrict__ Wq,
                              const float* __restrict__ Wk, const float* __restrict__ Wv)
{
    const int sel = blockIdx.y;
    const int blk = blockIdx.x;
    const float* src;
    __nv_bfloat16* hi;
    __nv_bfloat16* lo;
    int i;
    if (blk < XBLK) {
        i = blk * 256 + threadIdx.x;
        src = (sel == 0) ? q : (sel == 1) ? k : v;
        hi = g_xh + (size_t)sel * XSZ; lo = g_xl + (size_t)sel * XSZ;
    } else {
        i = (blk - XBLK) * 256 + threadIdx.x;
        src = (sel == 0) ? Wq : (sel == 1) ? Wk : Wv;
        hi = g_wh + (size_t)sel * WSZ; lo = g_wl + (size_t)sel * WSZ;
    }
    float4 x = ((const float4*)src)[i];
    __nv_bfloat162 h01, h23, l01, l23;
    split1(x.x, h01.x, l01.x); split1(x.y, h01.y, l01.y);
    split1(x.z, h23.x, l23.x); split1(x.w, h23.y, l23.y);
    ((__nv_bfloat162*)hi)[2 * i]     = h01;
    ((__nv_bfloat162*)hi)[2 * i + 1] = h23;
    ((__nv_bfloat162*)lo)[2 * i]     = l01;
    ((__nv_bfloat162*)lo)[2 * i + 1] = l23;
}

// ====== mma.sync projection GEMM: CTA 128x256, warp tile 64x64 (best: 241us) ===
#define GK        64
#define GPAD      72
#define NCHUNK    (DMODEL / GK)
#define BUFA      (128 * GPAD)
#define BUFB      (256 * GPAD)
#define STAGE_ELEMS (2 * BUFA + 2 * BUFB)
#define GEMM_SMEM (2 * STAGE_ELEMS * 2)

__global__ __launch_bounds__(256, 1) void gemm_kernel()
{
    extern __shared__ __nv_bfloat16 gsm[];
    const int sel = blockIdx.z;
    const int n0  = blockIdx.x * 256;
    const int m0  = blockIdx.y * 128;
    const int t   = threadIdx.x;
    const int w   = t >> 5, l = t & 31;

    const __nv_bfloat16* __restrict__ Ah = g_xh + (size_t)sel * XSZ;
    const __nv_bfloat16* __restrict__ Al = g_xl + (size_t)sel * XSZ;
    const __nv_bfloat16* __restrict__ Bh = g_wh + (size_t)sel * WSZ;
    const __nv_bfloat16* __restrict__ Bl = g_wl + (size_t)sel * WSZ;

    auto issue = [&](int c, int s) {
        __nv_bfloat16* base = gsm + s * STAGE_ELEMS;
        const int k0 = c * GK;
#pragma unroll
        for (int i = 0; i < 8; i++) {
            const int cid = t + i * 256;
            const int buf = cid >> 10;
            const int row = (cid >> 3) & 127;
            const int seg = cid & 7;
            const __nv_bfloat16* src = (buf ? Al : Ah) + (size_t)(m0 + row) * DMODEL + k0 + seg * 8;
            CP_ASYNC16(smem_u32(base + buf * BUFA + row * GPAD + seg * 8), src);
        }
#pragma unroll
        for (int i = 0; i < 16; i++) {
            const int cid = t + i * 256;
            const int buf = cid >> 11;
            const int row = (cid >> 3) & 255;
            const int seg = cid & 7;
            const __nv_bfloat16* src = (buf ? Bl : Bh) + (size_t)(n0 + row) * DMODEL + k0 + seg * 8;
            CP_ASYNC16(smem_u32(base + 2 * BUFA + buf * BUFB + row * GPAD + seg * 8), src);
        }
        CP_COMMIT();
    };

    const int wm = (w >> 2) * 64;
    const int wn = (w & 3) * 64;
    const int laneRowA = l & 15;
    const int laneColA = (l >> 4) * 8;
    const int laneRowB = (l >> 4) * 8 + (l & 7);
    const int laneColB = ((l >> 3) & 1) * 8;

    float acc[4][8][4];
#pragma unroll
    for (int mf = 0; mf < 4; mf++)
#pragma unroll
        for (int nf = 0; nf < 8; nf++)
#pragma unroll
            for (int i = 0; i < 4; i++) acc[mf][nf][i] = 0.f;

    issue(0, 0);

    for (int c = 0; c < NCHUNK; c++) {
        if (c + 1 < NCHUNK) { issue(c + 1, (c + 1) & 1); CP_WAIT1(); }
        else                { CP_WAIT0(); }
        __syncthreads();

        const uint32_t stage = smem_u32(gsm) + (uint32_t)((c & 1) * STAGE_ELEMS) * 2;
        const uint32_t xh0 = stage;
        const uint32_t xl0 = stage + BUFA * 2;
        const uint32_t wh0 = stage + 2 * BUFA * 2;
        const uint32_t wl0 = stage + 2 * BUFA * 2 + BUFB * 2;

#pragma unroll
        for (int ks = 0; ks < 4; ks++) {
            const int kc = ks * 16;
            uint32_t ah[4][4], al[4][4];
#pragma unroll
            for (int mf = 0; mf < 4; mf++) {
                const uint32_t off = (uint32_t)((wm + mf * 16 + laneRowA) * GPAD + kc + laneColA) * 2;
                LDSM_X4(ah[mf][0], ah[mf][1], ah[mf][2], ah[mf][3], xh0 + off);
                LDSM_X4(al[mf][0], al[mf][1], al[mf][2], al[mf][3], xl0 + off);
            }
#pragma unroll
            for (int half = 0; half < 2; half++) {
                uint32_t bh[2][4], bl[2][4];
#pragma unroll
                for (int gg = 0; gg < 2; gg++) {
                    const int g2 = half * 2 + gg;
                    const uint32_t off = (uint32_t)((wn + g2 * 16 + laneRowB) * GPAD + kc + laneColB) * 2;
                    LDSM_X4(bh[gg][0], bh[gg][1], bh[gg][2], bh[gg][3], wh0 + off);
                    LDSM_X4(bl[gg][0], bl[gg][1], bl[gg][2], bl[gg][3], wl0 + off);
                }
#pragma unroll
                for (int mf = 0; mf < 4; mf++) {
#pragma unroll
                    for (int nfl = 0; nfl < 4; nfl++) {
                        const int nf = half * 4 + nfl;
                        const int gg = nfl >> 1, hb = (nfl & 1) * 2;
                        float* a4 = acc[mf][nf];
                        MMA_BF16(a4[0], a4[1], a4[2], a4[3],
                                 ah[mf][0], ah[mf][1], ah[mf][2], ah[mf][3],
                                 bh[gg][hb], bh[gg][hb + 1]);
                        MMA_BF16(a4[0], a4[1], a4[2], a4[3],
                                 ah[mf][0], ah[mf][1], ah[mf][2], ah[mf][3],
                                 bl[gg][hb], bl[gg][hb + 1]);
                        MMA_BF16(a4[0], a4[1], a4[2], a4[3],
                                 al[mf][0], al[mf][1], al[mf][2], al[mf][3],
                                 bh[gg][hb], bh[gg][hb + 1]);
                    }
                }
            }
        }
        __syncthreads();
    }

    const int cr = l >> 2;
    const int cc = (l & 3) * 2;
#pragma unroll
    for (int mf = 0; mf < 4; mf++) {
#pragma unroll
        for (int nf = 0; nf < 8; nf++) {
            const int row = m0 + wm + mf * 16 + cr;
            const int col = n0 + wn + nf * 8 + cc;
            float a0 = acc[mf][nf][0], a1 = acc[mf][nf][1];
            float a2 = acc[mf][nf][2], a3 = acc[mf][nf][3];
            if (sel == 2) {
                float2 v0; v0.x = a0; v0.y = a1;
                float2 v1; v1.x = a2; v1.y = a3;
                *(float2*)&g_vw[(size_t)row * DMODEL + col]       = v0;
                *(float2*)&g_vw[(size_t)(row + 8) * DMODEL + col] = v1;
                const int b = row >> 11, sq = row & 2047;
                const int hh = col >> 6, dd = col & 63;
                const size_t tb = (size_t)(b * NHEADS + hh) * 64;
                __nv_bfloat16 h, lo2;
                split1(a0, h, lo2);
                g_vth[(tb + dd) * LSEQ + sq] = h;     g_vtl[(tb + dd) * LSEQ + sq] = lo2;
                split1(a1, h, lo2);
                g_vth[(tb + dd + 1) * LSEQ + sq] = h; g_vtl[(tb + dd + 1) * LSEQ + sq] = lo2;
                split1(a2, h, lo2);
                g_vth[(tb + dd) * LSEQ + sq + 8] = h; g_vtl[(tb + dd) * LSEQ + sq + 8] = lo2;
                split1(a3, h, lo2);
                g_vth[(tb + dd + 1) * LSEQ + sq + 8] = h; g_vtl[(tb + dd + 1) * LSEQ + sq + 8] = lo2;
            } else {
                __nv_bfloat16* H;
                __nv_bfloat16* L;
                if (sel == 1) { H = g_ksh; L = g_ksl; }
                else {
                    H = g_qsh; L = g_qsl;
                    a0 *= CSC; a1 *= CSC; a2 *= CSC; a3 *= CSC;
                }
                __nv_bfloat162 h0, l0, h1, l1;
                split1(a0, h0.x, l0.x); split1(a1, h0.y, l0.y);
                split1(a2, h1.x, l1.x); split1(a3, h1.y, l1.y);
                *(__nv_bfloat162*)&H[(size_t)row * DMODEL + col]       = h0;
                *(__nv_bfloat162*)&L[(size_t)row * DMODEL + col]       = l0;
                *(__nv_bfloat162*)&H[(size_t)(row + 8) * DMODEL + col] = h1;
                *(__nv_bfloat162*)&L[(size_t)(row + 8) * DMODEL + col] = l1;
            }
        }
    }
}

// ---------------- per-batch mask stats ----------------------------------------
__global__ void mask_stats_kernel(const float* __restrict__ v_mask)
{
    const int b = blockIdx.x;
    const int t = threadIdx.x;
    __shared__ int   smax[256];
    __shared__ float scnt[256];
    int   km = -1;
    float c  = 0.f;
    for (int k = t; k < LSEQ; k += 256) {
        if (v_mask[(size_t)b * LSEQ + k] != 0.f) { km = k; c += 1.f; }
    }
    smax[t] = km; scnt[t] = c;
    __syncthreads();
    for (int s = 128; s > 0; s >>= 1) {
        if (t < s) {
            smax[t] = max(smax[t], smax[t + s]);
            scnt[t] += scnt[t + s];
        }
        __syncthreads();
    }
    if (t == 0) {
        g_kmax[b] = (smax[0] < 0) ? 0 : smax[0];
        g_cnt[b]  = scnt[0];
    }
}

// ========= tensor-core flash attention: q-tile 128, true 2 CTAs/SM =============
// SMEM overlay: KV stage1 reuses the Q staging region (Q fragments live in
// registers before the first stage1 write). Per-tile work split in two
// nf-halves to cut live registers (~120 <= 128 cap). smem 74,240B -> 2 CTAs.
#define AP 72
#define KVBUF (64 * AP)                          // 4608 elements per buffer
#define STG   (4 * KVBUF)                        // 18432 elements per stage
#define ATTN_SMEM (2 * STG * 2 + 2 * 64 * 4)     // 74,240 bytes

__global__ __launch_bounds__(256, 2) void attn_kernel(const float* __restrict__ v_mask,
                                                      const float* __restrict__ q_mask,
                                                      float* __restrict__ out)
{
    extern __shared__ __nv_bfloat16 ash[];
    // stage0: ash[0 .. STG), stage1 (overlays Q): ash[STG .. 2*STG)
    __nv_bfloat16* Qh = ash + STG;                // Q staged in stage1 region
    __nv_bfloat16* Ql = ash + STG + 2 * KVBUF;
    float* vms = (float*)(ash + 2 * STG);         // [stage][64]

    const int qt = blockIdx.x, h = blockIdx.y, b = blockIdx.z;
    const int t = threadIdx.x, w = t >> 5, l = t & 31;

    const size_t kbase  = (size_t)b * LSEQ * DMODEL + h * 64;
    const size_t vtbase = (size_t)(b * NHEADS + h) * 64 * LSEQ;
    const size_t vmbase = (size_t)b * LSEQ;

    auto issueKV = [&](int kt, int st) {
#pragma unroll
        for (int i = 0; i < 8; i++) {
            const int cid = t + i * 256;
            const int buf = cid >> 9;
            const int row = (cid >> 3) & 63;
            const int s8  = cid & 7;
            const __nv_bfloat16* src;
            if      (buf == 0) src = g_ksh + kbase + (size_t)(kt * 64 + row) * DMODEL + s8 * 8;
            else if (buf == 1) src = g_ksl + kbase + (size_t)(kt * 64 + row) * DMODEL + s8 * 8;
            else if (buf == 2) src = g_vth + vtbase + (size_t)row * LSEQ + kt * 64 + s8 * 8;
            else               src = g_vtl + vtbase + (size_t)row * LSEQ + kt * 64 + s8 * 8;
            CP_ASYNC16(smem_u32(ash + (size_t)(st * 4 + buf) * KVBUF + row * AP + s8 * 8), src);
        }
        if (t < 16)
            CP_ASYNC16(smem_u32(vms + st * 64 + t * 4), v_mask + vmbase + kt * 64 + t * 4);
        CP_COMMIT();
    };

    // ---- stage Q (128x64 hi/lo) into the stage1 region ----
    {
#pragma unroll
        for (int i = 0; i < 8; i++) {
            const int cid = t + i * 256;
            const int hl  = cid >> 10;
            const int row = (cid >> 3) & 127;
            const int s8  = cid & 7;
            const size_t goff = ((size_t)(b * LSEQ + qt * 128 + row)) * DMODEL + h * 64 + s8 * 8;
            const __nv_bfloat16* src = hl ? (g_qsl + goff) : (g_qsh + goff);
            __nv_bfloat16* dst = hl ? (Ql + row * AP + s8 * 8) : (Qh + row * AP + s8 * 8);
            CP_ASYNC16(smem_u32(dst), src);
        }
        CP_COMMIT();
    }

    const int kt0 = qt * 2;
    issueKV(kt0, 0);          // stage0 does NOT overlap Q
    CP_WAIT0();
    __syncthreads();

    const int laneRowA = l & 15;
    const int laneColA = (l >> 4) * 8;
    const int laneRowB = (l >> 4) * 8 + (l & 7);
    const int laneColB = ((l >> 3) & 1) * 8;

    // Q fragments -> registers; Q smem is dead afterwards
    uint32_t aQh[4][4], aQl[4][4];
#pragma unroll
    for (int ks = 0; ks < 4; ks++) {
        const uint32_t off = (uint32_t)((w * 16 + laneRowA) * AP + ks * 16 + laneColA) * 2;
        LDSM_X4(aQh[ks][0], aQh[ks][1], aQh[ks][2], aQh[ks][3], smem_u32(Qh) + off);
        LDSM_X4(aQl[ks][0], aQl[ks][1], aQl[ks][2], aQl[ks][3], smem_u32(Ql) + off);
    }

    float sO[8][4];
#pragma unroll
    for (int df = 0; df < 8; df++)
#pragma unroll
        for (int i = 0; i < 4; i++) sO[df][i] = 0.f;
    float l0 = 0.f, l1 = 0.f;

    const int qrow0 = qt * 128 + w * 16 + (l >> 2);
    const int qrow1 = qrow0 + 8;

    for (int kt = kt0; kt < NKT; kt++) {
        const int st = (kt - kt0) & 1;
        if (kt > kt0) { CP_WAIT0(); }
        __syncthreads();   // all warps done with previous stage (and Q frags on iter 0)
        if (kt + 1 < NKT) issueKV(kt + 1, st ^ 1);

        const uint32_t Khs = smem_u32(ash + (size_t)(st * 4 + 0) * KVBUF);
        const uint32_t Kls = smem_u32(ash + (size_t)(st * 4 + 1) * KVBUF);
        const uint32_t Vhs = smem_u32(ash + (size_t)(st * 4 + 2) * KVBUF);
        const uint32_t Vls = smem_u32(ash + (size_t)(st * 4 + 3) * KVBUF);
        const float* vmsb = vms + st * 64;
        const bool diag = (kt <= kt0 + 1);

        // ---- two nf-halves: S -> softmax -> PV, low register footprint ----
#pragma unroll
        for (int half = 0; half < 2; half++) {
            float s[4][4];
#pragma unroll
            for (int j = 0; j < 4; j++)
#pragma unroll
                for (int i = 0; i < 4; i++) s[j][i] = 0.f;

#pragma unroll
            for (int ks = 0; ks < 4; ks++) {
                uint32_t kbh[2][4], kbl[2][4];
#pragma unroll
                for (int gg = 0; gg < 2; gg++) {
                    const int g2 = half * 2 + gg;
                    const uint32_t off = (uint32_t)((g2 * 16 + laneRowB) * AP + ks * 16 + laneColB) * 2;
                    LDSM_X4(kbh[gg][0], kbh[gg][1], kbh[gg][2], kbh[gg][3], Khs + off);
                    LDSM_X4(kbl[gg][0], kbl[gg][1], kbl[gg][2], kbl[gg][3], Kls + off);
                }
#pragma unroll
                for (int j = 0; j < 4; j++) {
                    const int gg = j >> 1, hb = (j & 1) * 2;
                    float* a4 = s[j];
                    MMA_BF16(a4[0], a4[1], a4[2], a4[3],
                             aQh[ks][0], aQh[ks][1], aQh[ks][2], aQh[ks][3],
                             kbh[gg][hb], kbh[gg][hb + 1]);
                    MMA_BF16(a4[0], a4[1], a4[2], a4[3],
                             aQh[ks][0], aQh[ks][1], aQh[ks][2], aQh[ks][3],
                             kbl[gg][hb], kbl[gg][hb + 1]);
                    MMA_BF16(a4[0], a4[1], a4[2], a4[3],
                             aQl[ks][0], aQl[ks][1], aQl[ks][2], aQl[ks][3],
                             kbh[gg][hb], kbh[gg][hb + 1]);
                }
            }

            // softmax on this half
            if (diag) {
#pragma unroll
                for (int j = 0; j < 4; j++) {
                    const int nf = half * 4 + j;
                    const int cl0 = nf * 8 + 2 * (l & 3);
                    const float vm0 = vmsb[cl0], vm1 = vmsb[cl0 + 1];
                    const int c0 = kt * 64 + cl0, c1 = c0 + 1;
                    const float m00 = (c0 > qrow0) ? vm0 : 0.f;
                    const float m10 = (c1 > qrow0) ? vm1 : 0.f;
                    const float m01 = (c0 > qrow1) ? vm0 : 0.f;
                    const float m11 = (c1 > qrow1) ? vm1 : 0.f;
                    float p0 = fexp2nc(s[j][0]) * m00;
                    float p1 = fexp2nc(s[j][1]) * m10;
                    float p2 = fexp2nc(s[j][2]) * m01;
                    float p3 = fexp2nc(s[j][3]) * m11;
                    l0 += p0 + p1;
                    l1 += p2 + p3;
                    s[j][0] = p0; s[j][1] = p1; s[j][2] = p2; s[j][3] = p3;
                }
            } else {
#pragma unroll
                for (int j = 0; j < 4; j++) {
                    const int nf = half * 4 + j;
                    const int cl0 = nf * 8 + 2 * (l & 3);
                    const float vm0 = vmsb[cl0], vm1 = vmsb[cl0 + 1];
                    float p0 = fexp2nc(s[j][0]) * vm0;
                    float p1 = fexp2nc(s[j][1]) * vm1;
                    float p2 = fexp2nc(s[j][2]) * vm0;
                    float p3 = fexp2nc(s[j][3]) * vm1;
                    l0 += p0 + p1;
                    l1 += p2 + p3;
                    s[j][0] = p0; s[j][1] = p1; s[j][2] = p2; s[j][3] = p3;
                }
            }

            // PV for the kv chunks covered by this half (kv = 2*half, 2*half+1)
#pragma unroll
            for (int kk = 0; kk < 2; kk++) {
                const int kv = half * 2 + kk;
                uint32_t aPh[4], aPl[4];
                packsplit2(s[2 * kk][0],     s[2 * kk][1],     aPh[0], aPl[0]);
                packsplit2(s[2 * kk][2],     s[2 * kk][3],     aPh[1], aPl[1]);
                packsplit2(s[2 * kk + 1][0], s[2 * kk + 1][1], aPh[2], aPl[2]);
                packsplit2(s[2 * kk + 1][2], s[2 * kk + 1][3], aPh[3], aPl[3]);
                uint32_t vbh[4][4], vbl[4][4];
#pragma unroll
                for (int g2 = 0; g2 < 4; g2++) {
                    const uint32_t off = (uint32_t)((g2 * 16 + laneRowB) * AP + kv * 16 + laneColB) * 2;
                    LDSM_X4(vbh[g2][0], vbh[g2][1], vbh[g2][2], vbh[g2][3], Vhs + off);
                    LDSM_X4(vbl[g2][0], vbl[g2][1], vbl[g2][2], vbl[g2][3], Vls + off);
                }
#pragma unroll
                for (int df = 0; df < 8; df++) {
                    const int g2 = df >> 1, hb = (df & 1) * 2;
                    float* a4 = sO[df];
                    MMA_BF16(a4[0], a4[1], a4[2], a4[3],
                             aPh[0], aPh[1], aPh[2], aPh[3],
                             vbh[g2][hb], vbh[g2][hb + 1]);
                    MMA_BF16(a4[0], a4[1], a4[2], a4[3],
                             aPh[0], aPh[1], aPh[2], aPh[3],
                             vbl[g2][hb], vbl[g2][hb + 1]);
                    MMA_BF16(a4[0], a4[1], a4[2], a4[3],
                             aPl[0], aPl[1], aPl[2], aPl[3],
                             vbh[g2][hb], vbh[g2][hb + 1]);
                }
            }
        }
    }

    l0 += __shfl_xor_sync(0xffffffffu, l0, 1);
    l0 += __shfl_xor_sync(0xffffffffu, l0, 2);
    l1 += __shfl_xor_sync(0xffffffffu, l1, 1);
    l1 += __shfl_xor_sync(0xffffffffu, l1, 2);
    const float sc0 = ((l0 > 0.f) ? (1.f / l0) : 0.f) * q_mask[(size_t)b * LSEQ + qrow0];
    const float sc1 = ((l1 > 0.f) ? (1.f / l1) : 0.f) * q_mask[(size_t)b * LSEQ + qrow1];
#pragma unroll
    for (int df = 0; df < 8; df++) {
        const int d = df * 8 + 2 * (l & 3);
        float2 o0; o0.x = sO[df][0] * sc0; o0.y = sO[df][1] * sc0;
        float2 o1; o1.x = sO[df][2] * sc1; o1.y = sO[df][3] * sc1;
        *(float2*)&out[((size_t)b * LSEQ + qrow0) * DMODEL + h * 64 + d] = o0;
        *(float2*)&out[((size_t)b * LSEQ + qrow1) * DMODEL + h * 64 + d] = o1;
    }
}

// --------- fallback: rows q >= kmax -> uniform mean over penalty==-1e10 set ----
__global__ void fallback_kernel(const float* __restrict__ v_mask,
                                const float* __restrict__ q_mask,
                                float* __restrict__ out)
{
    const int b   = blockIdx.x;
    const int dim = blockIdx.y * blockDim.x + threadIdx.x;
    const int   kmax = g_kmax[b];
    const float cnt1 = g_cnt[b];
    const float* vw = g_vw + (size_t)b * LSEQ * DMODEL;

    float s1 = 0.f;
    for (int k = 0; k < LSEQ; k++)
        s1 += v_mask[(size_t)b * LSEQ + k] * vw[(size_t)k * DMODEL + dim];

    float suff = 0.f;
    for (int q = LSEQ - 1; q >= kmax; q--) {
        const float denom = cnt1 + (float)(LSEQ - 1 - q);
        const float val = (denom > 0.f) ? (s1 + suff) / denom : 0.f;
        out[((size_t)b * LSEQ + q) * DMODEL + dim] = val * q_mask[(size_t)b * LSEQ + q];
        suff += vw[(size_t)q * DMODEL + dim];
    }
}

// -------------------------------- launch ---------------------------------------
extern "C" void kernel_launch(void* const* d_in, const int* in_sizes, int n_in,
                              void* d_out, int out_size)
{
    const float* q      = (const float*)d_in[0];
    const float* k      = (const float*)d_in[1];
    const float* v      = (const float*)d_in[2];
    const float* v_mask = (const float*)d_in[3];
    const float* q_mask = (const float*)d_in[4];
    const float* Wq     = (const float*)d_in[5];
    const float* Wk     = (const float*)d_in[6];
    const float* Wv     = (const float*)d_in[7];
    float* out = (float*)d_out;

    cudaFuncSetAttribute(gemm_kernel, cudaFuncAttributeMaxDynamicSharedMemorySize, GEMM_SMEM);
    cudaFuncSetAttribute(attn_kernel, cudaFuncAttributeMaxDynamicSharedMemorySize, ATTN_SMEM);

    // launch 0: all splits in one go
    split3_kernel<<<dim3(XBLK + WBLK, 3), 256>>>(q, k, v, Wq, Wk, Wv);

    // launch 1
    dim3 gg(DMODEL / 256, MROWS / 128, 3);
    gemm_kernel<<<gg, 256, GEMM_SMEM>>>();

    // launch 2
    mask_stats_kernel<<<BATCH, 256>>>(v_mask);

    // launch 3 (ncu capture slot)
    dim3 ag(NQT, NHEADS, BATCH);
    attn_kernel<<<ag, 256, ATTN_SMEM>>>(v_mask, q_mask, out);

    // launch 4
    fallback_kernel<<<dim3(BATCH, DMODEL / 128), 128>>>(v_mask, q_mask, out);
}